// round 1
// baseline (speedup 1.0000x reference)
#include <cuda_runtime.h>
#include <cuda_bf16.h>

// Problem constants
#define Bz  4
#define Sz  2048
#define Dz  1024
#define Hz  16
#define HDz 64
#define Mz  (Bz*Sz)   // 8192

// Scratch (allocations forbidden -> __device__ globals). 4 x 33.5 MB = 134 MB.
__device__ float g_q[(size_t)Bz*Hz*Sz*HDz];
__device__ float g_k[(size_t)Bz*Hz*Sz*HDz];
__device__ float g_v[(size_t)Bz*Hz*Sz*HDz];
__device__ float g_att[(size_t)Bz*Sz*Dz];

// ---------------------------------------------------------------------------
// C = X @ W^T  (X: [8192,1024] row-major, W: [1024,1024] row-major, K=1024)
// 128x128 block tile, BK=16, 256 threads, 8x8 per thread.
// split_heads: write out in [B,H,S,HD] layout (for Q/K/V), else [M,N].
// ---------------------------------------------------------------------------
__global__ __launch_bounds__(256) void gemm_nt(
    const float* __restrict__ X, const float* __restrict__ W,
    float* __restrict__ out, float scale, int split_heads)
{
    __shared__ float As[16][128];   // [k][m]
    __shared__ float Bs[16][128];   // [k][n]

    const int tid = threadIdx.x;
    const int tx  = tid & 15;       // 0..15
    const int ty  = tid >> 4;       // 0..15
    const int m0  = blockIdx.y * 128;
    const int n0  = blockIdx.x * 128;

    float acc[8][8];
#pragma unroll
    for (int i = 0; i < 8; i++)
#pragma unroll
        for (int j = 0; j < 8; j++) acc[i][j] = 0.f;

    for (int kt = 0; kt < Dz; kt += 16) {
        // Load 128x16 tiles of X and W, stored k-major (transposed) in SMEM.
#pragma unroll
        for (int l = 0; l < 2; l++) {
            int v   = tid + l * 256;      // 0..511 (512 float4 per tile)
            int row = v >> 2;             // 0..127
            int kc  = (v & 3) << 2;       // 0,4,8,12
            float4 a4 = *(const float4*)(X + (size_t)(m0 + row) * Dz + kt + kc);
            As[kc+0][row] = a4.x; As[kc+1][row] = a4.y;
            As[kc+2][row] = a4.z; As[kc+3][row] = a4.w;
            float4 b4 = *(const float4*)(W + (size_t)(n0 + row) * Dz + kt + kc);
            Bs[kc+0][row] = b4.x; Bs[kc+1][row] = b4.y;
            Bs[kc+2][row] = b4.z; Bs[kc+3][row] = b4.w;
        }
        __syncthreads();

#pragma unroll
        for (int kk = 0; kk < 16; kk++) {
            float a[8], b[8];
            *(float4*)(a)     = *(float4*)(&As[kk][ty * 8]);
            *(float4*)(a + 4) = *(float4*)(&As[kk][ty * 8 + 4]);
            *(float4*)(b)     = *(float4*)(&Bs[kk][tx * 8]);
            *(float4*)(b + 4) = *(float4*)(&Bs[kk][tx * 8 + 4]);
#pragma unroll
            for (int i = 0; i < 8; i++)
#pragma unroll
                for (int j = 0; j < 8; j++)
                    acc[i][j] = fmaf(a[i], b[j], acc[i][j]);
        }
        __syncthreads();
    }

    // Epilogue
    if (split_heads) {
        // out[((b*H + h)*S + s)*HD + hd]; 8-col groups never cross a head (8|64)
#pragma unroll
        for (int i = 0; i < 8; i++) {
            int m  = m0 + ty * 8 + i;
            int bb = m / Sz, s = m % Sz;
            int nbase = n0 + tx * 8;
            int h   = nbase >> 6;
            int hd0 = nbase & 63;
            float* dst = out + (((size_t)(bb * Hz + h)) * Sz + s) * HDz + hd0;
#pragma unroll
            for (int j4 = 0; j4 < 2; j4++) {
                float4 r;
                r.x = acc[i][j4*4+0] * scale; r.y = acc[i][j4*4+1] * scale;
                r.z = acc[i][j4*4+2] * scale; r.w = acc[i][j4*4+3] * scale;
                *(float4*)(dst + j4 * 4) = r;
            }
        }
    } else {
#pragma unroll
        for (int i = 0; i < 8; i++) {
            int m = m0 + ty * 8 + i;
            float* dst = out + (size_t)m * Dz + n0 + tx * 8;
#pragma unroll
            for (int j4 = 0; j4 < 2; j4++) {
                float4 r;
                r.x = acc[i][j4*4+0] * scale; r.y = acc[i][j4*4+1] * scale;
                r.z = acc[i][j4*4+2] * scale; r.w = acc[i][j4*4+3] * scale;
                *(float4*)(dst + j4 * 4) = r;
            }
        }
    }
}

// ---------------------------------------------------------------------------
// Flash attention: one CTA per (b, h, 64-row q tile).
// Q/K in SMEM k-major (transposed), V natural. P reuses the K buffer.
// Online softmax, width-16 shuffle reductions. Output -> g_att [B,S,D].
// ---------------------------------------------------------------------------
__global__ __launch_bounds__(256) void attn_kernel(
    const float* __restrict__ bias,
    const float* __restrict__ Q,
    const float* __restrict__ K,
    const float* __restrict__ V,
    float* __restrict__ out)
{
    __shared__ float QsT[64][64];   // [hd][r]
    __shared__ float KsT[64][64];   // [hd][c], reused as Ps[c][r] after GEMM1
    __shared__ float Vs [64][64];   // [c][hd]

    const int tid = threadIdx.x;
    const int tx  = tid & 15;       // score col / d-col group
    const int ty  = tid >> 4;       // row group
    const int q0  = blockIdx.x * 64;
    const int h   = blockIdx.y;
    const int b   = blockIdx.z;

    const float* Qp = Q + ((size_t)(b * Hz + h)) * Sz * HDz;
    const float* Kp = K + ((size_t)(b * Hz + h)) * Sz * HDz;
    const float* Vp = V + ((size_t)(b * Hz + h)) * Sz * HDz;
    const float* biasp = bias + (size_t)b * Sz * Sz;

    // Load Q tile transposed (64 rows x 64 hd, 16 float4/row)
    for (int v = tid; v < 64 * 16; v += 256) {
        int row = v >> 4;
        int c4  = (v & 15) << 2;
        float4 q4 = *(const float4*)(Qp + (size_t)(q0 + row) * HDz + c4);
        QsT[c4+0][row] = q4.x; QsT[c4+1][row] = q4.y;
        QsT[c4+2][row] = q4.z; QsT[c4+3][row] = q4.w;
    }

    float o[4][4];
    float mrow[4], lrow[4];
#pragma unroll
    for (int i = 0; i < 4; i++) {
        mrow[i] = -1e30f; lrow[i] = 0.f;
#pragma unroll
        for (int j = 0; j < 4; j++) o[i][j] = 0.f;
    }

    for (int k0 = 0; k0 < Sz; k0 += 64) {
        __syncthreads();   // prior-iter reads of KsT/Vs done (also covers Q load, iter 0)
        for (int v = tid; v < 64 * 16; v += 256) {
            int row = v >> 4;
            int c4  = (v & 15) << 2;
            float4 k4 = *(const float4*)(Kp + (size_t)(k0 + row) * HDz + c4);
            KsT[c4+0][row] = k4.x; KsT[c4+1][row] = k4.y;
            KsT[c4+2][row] = k4.z; KsT[c4+3][row] = k4.w;
            *(float4*)(&Vs[row][c4]) = *(const float4*)(Vp + (size_t)(k0 + row) * HDz + c4);
        }
        __syncthreads();

        // S = Q K^T + bias   (4x4 fragment per thread)
        float s[4][4];
#pragma unroll
        for (int i = 0; i < 4; i++) {
            float4 b4 = *(const float4*)(biasp + (size_t)(q0 + ty*4 + i) * Sz + k0 + tx*4);
            s[i][0] = b4.x; s[i][1] = b4.y; s[i][2] = b4.z; s[i][3] = b4.w;
        }
#pragma unroll 8
        for (int kk = 0; kk < 64; kk++) {
            float4 a4 = *(float4*)(&QsT[kk][ty * 4]);
            float4 c4 = *(float4*)(&KsT[kk][tx * 4]);
            float a[4] = {a4.x, a4.y, a4.z, a4.w};
            float c[4] = {c4.x, c4.y, c4.z, c4.w};
#pragma unroll
            for (int i = 0; i < 4; i++)
#pragma unroll
                for (int j = 0; j < 4; j++)
                    s[i][j] = fmaf(a[i], c[j], s[i][j]);
        }
        __syncthreads();   // all GEMM1 reads of KsT complete before P overwrites it

        // Online softmax; write P (c-major) into the K buffer
        float* Ps = &KsT[0][0];
#pragma unroll
        for (int i = 0; i < 4; i++) {
            float mx = fmaxf(fmaxf(s[i][0], s[i][1]), fmaxf(s[i][2], s[i][3]));
#pragma unroll
            for (int off = 8; off >= 1; off >>= 1)
                mx = fmaxf(mx, __shfl_xor_sync(0xffffffffu, mx, off, 16));
            float mnew  = fmaxf(mrow[i], mx);
            float alpha = __expf(mrow[i] - mnew);
            mrow[i] = mnew;
            float ps = 0.f;
#pragma unroll
            for (int j = 0; j < 4; j++) {
                float p = __expf(s[i][j] - mnew);
                ps += p;
                Ps[(tx * 4 + j) * 64 + (ty * 4 + i)] = p;
            }
#pragma unroll
            for (int off = 8; off >= 1; off >>= 1)
                ps += __shfl_xor_sync(0xffffffffu, ps, off, 16);
            lrow[i] = lrow[i] * alpha + ps;
            o[i][0] *= alpha; o[i][1] *= alpha; o[i][2] *= alpha; o[i][3] *= alpha;
        }
        __syncthreads();   // P fully written

        // O += P @ V
#pragma unroll 8
        for (int c = 0; c < 64; c++) {
            float4 p4 = *(float4*)(Ps + c * 64 + ty * 4);
            float4 v4 = *(float4*)(&Vs[c][tx * 4]);
            float pa[4] = {p4.x, p4.y, p4.z, p4.w};
            float vb[4] = {v4.x, v4.y, v4.z, v4.w};
#pragma unroll
            for (int i = 0; i < 4; i++)
#pragma unroll
                for (int j = 0; j < 4; j++)
                    o[i][j] = fmaf(pa[i], vb[j], o[i][j]);
        }
    }

    // Normalize and write merged-head layout [B,S,D]
#pragma unroll
    for (int i = 0; i < 4; i++) {
        float inv = 1.0f / lrow[i];
        int m = q0 + ty * 4 + i;
        float4 r;
        r.x = o[i][0] * inv; r.y = o[i][1] * inv;
        r.z = o[i][2] * inv; r.w = o[i][3] * inv;
        *(float4*)(out + ((size_t)b * Sz + m) * Dz + h * HDz + tx * 4) = r;
    }
}

// ---------------------------------------------------------------------------
// Launch: 3 projections -> attention -> output projection (5 kernels, all
// graph-capturable, no allocations, no syncs).
// ---------------------------------------------------------------------------
extern "C" void kernel_launch(void* const* d_in, const int* in_sizes, int n_in,
                              void* d_out, int out_size)
{
    const float* query = (const float*)d_in[0];
    const float* key_  = (const float*)d_in[1];
    const float* value = (const float*)d_in[2];
    const float* bias  = (const float*)d_in[3];
    const float* Wq    = (const float*)d_in[4];
    const float* Wk    = (const float*)d_in[5];
    const float* Wv    = (const float*)d_in[6];
    const float* Wo    = (const float*)d_in[7];

    float *qp, *kp, *vp, *ap;
    cudaGetSymbolAddress((void**)&qp, g_q);
    cudaGetSymbolAddress((void**)&kp, g_k);
    cudaGetSymbolAddress((void**)&vp, g_v);
    cudaGetSymbolAddress((void**)&ap, g_att);

    dim3 gg(Dz / 128, Mz / 128);   // (8, 64)
    gemm_nt<<<gg, 256>>>(query, Wq, qp, 0.125f, 1);   // HD^-0.5 = 0.125
    gemm_nt<<<gg, 256>>>(key_,  Wk, kp, 1.0f, 1);
    gemm_nt<<<gg, 256>>>(value, Wv, vp, 1.0f, 1);

    attn_kernel<<<dim3(Sz / 64, Hz, Bz), 256>>>(bias, qp, kp, vp, ap);

    gemm_nt<<<gg, 256>>>(ap, Wo, (float*)d_out, 1.0f, 0);
}

// round 4
// speedup vs baseline: 1.3489x; 1.3489x over previous
#include <cuda_runtime.h>
#include <cuda_bf16.h>
#include <cstdint>

// Problem constants
#define Bz  4
#define Sz  2048
#define Dz  1024
#define Hz  16
#define HDz 64
#define Mz  (Bz*Sz)   // 8192

// Scratch (allocations forbidden -> __device__ globals).
__device__ float g_q[(size_t)Bz*Hz*Sz*HDz];
__device__ float g_k[(size_t)Bz*Hz*Sz*HDz];
__device__ float g_v[(size_t)Bz*Hz*Sz*HDz];
__device__ float g_att[(size_t)Bz*Sz*Dz];

// ===========================================================================
// Helpers
// ===========================================================================
__device__ __forceinline__ uint32_t smem_u32(const void* p) {
    uint32_t a;
    asm("{ .reg .u64 t; cvta.to.shared.u64 t, %1; cvt.u32.u64 %0, t; }"
        : "=r"(a) : "l"(p));
    return a;
}

// pack two floats into bf16x2: lo -> low 16 bits (memory-order element 0)
__device__ __forceinline__ uint32_t pack_bf16x2(float lo, float hi) {
    uint32_t r;
    asm("cvt.rn.bf16x2.f32 %0, %1, %2;" : "=r"(r) : "f"(hi), "f"(lo));
    return r;
}

__device__ __forceinline__ void ldmatrix_x4(uint32_t* r, uint32_t addr) {
    asm volatile("ldmatrix.sync.aligned.m8n8.x4.shared.b16 {%0,%1,%2,%3}, [%4];"
        : "=r"(r[0]), "=r"(r[1]), "=r"(r[2]), "=r"(r[3]) : "r"(addr));
}

__device__ __forceinline__ void mma_bf16(float* d, const uint32_t* a, const uint32_t* b) {
    asm volatile(
        "mma.sync.aligned.m16n8k16.row.col.f32.bf16.bf16.f32 "
        "{%0,%1,%2,%3}, {%4,%5,%6,%7}, {%8,%9}, {%0,%1,%2,%3};"
        : "+f"(d[0]), "+f"(d[1]), "+f"(d[2]), "+f"(d[3])
        : "r"(a[0]), "r"(a[1]), "r"(a[2]), "r"(a[3]), "r"(b[0]), "r"(b[1]));
}

// ===========================================================================
// Split-bf16 tensor-core GEMM: C[8192,1024] = X[8192,1024] @ W[1024,1024]^T
// 128x128 CTA tile, BK=32, 8 warps (4 in M x 2 in N), warp tile 32x64.
// 3 products: Ahi*Bhi + Ahi*Blo + Alo*Bhi (error ~2^-16 relative).
// Double-buffered SMEM + register prefetch of next chunk.
// SMEM tile layout: [128 rows][32 bf16], row = 64B, chunk c (16B) swizzled
// by c ^= (row>>1)&3.  Buffer b at b*32768: Ahi 0, Alo 8K, Bhi 16K, Blo 24K.
// ===========================================================================
#define GEMM_DSMEM (2 * 32768 + 1024)

__global__ __launch_bounds__(256) void gemm_tc(
    const float* __restrict__ X, const float* __restrict__ W,
    float* __restrict__ out, float scale, int split_heads)
{
    extern __shared__ __align__(16) char dsm[];
    const uint32_t sbase = (smem_u32(dsm) + 1023) & ~1023u;

    const int tid    = threadIdx.x;
    const int wid    = tid >> 5;
    const int lane   = tid & 31;
    const int warp_m = wid & 3;     // 0..3 -> m offset 32*warp_m
    const int warp_n = wid >> 2;    // 0..1 -> n offset 64*warp_n
    const int m0 = blockIdx.y * 128;
    const int n0 = blockIdx.x * 128;

    // loader indices (two 16B chunks per thread per matrix)
    const int lr0 = tid >> 2;            // rows 0..63
    const int lc  = tid & 3;             // chunk 0..3

    float acc[2][8][4];
#pragma unroll
    for (int i = 0; i < 2; i++)
#pragma unroll
        for (int j = 0; j < 8; j++)
#pragma unroll
            for (int t = 0; t < 4; t++) acc[i][j][t] = 0.f;

    // ---- prefetch chunk 0 into registers
    float4 xa[4], xb[4];
    {
        const int k0 = 0;
#pragma unroll
        for (int j = 0; j < 2; j++) {
            int r = lr0 + j * 64;
            const float* pa = X + (size_t)(m0 + r) * Dz + k0 + lc * 8;
            const float* pb = W + (size_t)(n0 + r) * Dz + k0 + lc * 8;
            xa[2*j]   = *(const float4*)(pa);
            xa[2*j+1] = *(const float4*)(pa + 4);
            xb[2*j]   = *(const float4*)(pb);
            xb[2*j+1] = *(const float4*)(pb + 4);
        }
    }

    for (int kc = 0; kc < 32; kc++) {
        const uint32_t bb = sbase + (kc & 1) * 32768;

        // ---- STS: convert + split + swizzled store
#pragma unroll
        for (int j = 0; j < 2; j++) {
            int r = lr0 + j * 64;
            uint32_t phys = (uint32_t)(r * 64 + ((lc ^ ((r >> 1) & 3)) << 4));
#pragma unroll
            for (int half = 0; half < 2; half++) {
                float4 v0 = half ? xb[2*j]   : xa[2*j];
                float4 v1 = half ? xb[2*j+1] : xa[2*j+1];
                uint32_t h0 = pack_bf16x2(v0.x, v0.y);
                uint32_t h1 = pack_bf16x2(v0.z, v0.w);
                uint32_t h2 = pack_bf16x2(v1.x, v1.y);
                uint32_t h3 = pack_bf16x2(v1.z, v1.w);
                uint32_t l0, l1, l2, l3;
                {
                    float ea = __uint_as_float(h0 << 16);
                    float eb = __uint_as_float(h0 & 0xffff0000u);
                    l0 = pack_bf16x2(v0.x - ea, v0.y - eb);
                    ea = __uint_as_float(h1 << 16);
                    eb = __uint_as_float(h1 & 0xffff0000u);
                    l1 = pack_bf16x2(v0.z - ea, v0.w - eb);
                    ea = __uint_as_float(h2 << 16);
                    eb = __uint_as_float(h2 & 0xffff0000u);
                    l2 = pack_bf16x2(v1.x - ea, v1.y - eb);
                    ea = __uint_as_float(h3 << 16);
                    eb = __uint_as_float(h3 & 0xffff0000u);
                    l3 = pack_bf16x2(v1.z - ea, v1.w - eb);
                }
                uint32_t base_hi = bb + (half ? 16384u : 0u) + phys;
                asm volatile("st.shared.v4.b32 [%0], {%1,%2,%3,%4};"
                    :: "r"(base_hi), "r"(h0), "r"(h1), "r"(h2), "r"(h3) : "memory");
                asm volatile("st.shared.v4.b32 [%0], {%1,%2,%3,%4};"
                    :: "r"(base_hi + 8192u), "r"(l0), "r"(l1), "r"(l2), "r"(l3) : "memory");
            }
        }
        __syncthreads();

        // ---- prefetch next chunk (latency overlapped with compute below)
        if (kc < 31) {
            const int k0 = (kc + 1) * 32;
#pragma unroll
            for (int j = 0; j < 2; j++) {
                int r = lr0 + j * 64;
                const float* pa = X + (size_t)(m0 + r) * Dz + k0 + lc * 8;
                const float* pb = W + (size_t)(n0 + r) * Dz + k0 + lc * 8;
                xa[2*j]   = *(const float4*)(pa);
                xa[2*j+1] = *(const float4*)(pa + 4);
                xb[2*j]   = *(const float4*)(pb);
                xb[2*j+1] = *(const float4*)(pb + 4);
            }
        }

        // ---- compute: 2 k16 steps
#pragma unroll
        for (int ks = 0; ks < 2; ks++) {
            uint32_t ahi[2][4], alo[2][4];
            const int cA = ks * 2 + (lane >> 4);
#pragma unroll
            for (int mt = 0; mt < 2; mt++) {
                int r = warp_m * 32 + mt * 16 + (lane & 15);
                uint32_t phys = (uint32_t)(r * 64 + ((cA ^ ((r >> 1) & 3)) << 4));
                ldmatrix_x4(ahi[mt], bb + phys);
                ldmatrix_x4(alo[mt], bb + 8192u + phys);
            }
            const int cB = ks * 2 + ((lane >> 3) & 1);
            const int rB = warp_n * 64 + (lane & 7) + ((lane & 16) >> 1);
#pragma unroll
            for (int np = 0; np < 4; np++) {
                uint32_t bh[4], bl[4];
                int r = rB + np * 16;
                uint32_t phys = (uint32_t)(r * 64 + ((cB ^ ((r >> 1) & 3)) << 4));
                ldmatrix_x4(bh, bb + 16384u + phys);
                ldmatrix_x4(bl, bb + 24576u + phys);
#pragma unroll
                for (int mt = 0; mt < 2; mt++) {
#pragma unroll
                    for (int half = 0; half < 2; half++) {
                        float* d = acc[mt][np * 2 + half];
                        mma_bf16(d, ahi[mt], bh + half * 2);   // Ahi*Bhi
                        mma_bf16(d, ahi[mt], bl + half * 2);   // Ahi*Blo
                        mma_bf16(d, alo[mt], bh + half * 2);   // Alo*Bhi
                    }
                }
            }
        }
        __syncthreads();
    }

    // ---- epilogue: direct STG of fp32 accumulators
    const int r0 = lane >> 2;
    const int c0 = (lane & 3) * 2;
#pragma unroll
    for (int mt = 0; mt < 2; mt++) {
#pragma unroll
        for (int nt = 0; nt < 8; nt++) {
#pragma unroll
            for (int rr = 0; rr < 2; rr++) {
                int m = m0 + warp_m * 32 + mt * 16 + r0 + rr * 8;
                int n = n0 + warp_n * 64 + nt * 8 + c0;
                float2 v;
                v.x = acc[mt][nt][rr * 2 + 0] * scale;
                v.y = acc[mt][nt][rr * 2 + 1] * scale;
                float* dst;
                if (split_heads) {
                    int b = m >> 11, s = m & (Sz - 1);
                    int h = n >> 6, hd = n & 63;
                    dst = out + (((size_t)(b * Hz + h)) * Sz + s) * HDz + hd;
                } else {
                    dst = out + (size_t)m * Dz + n;
                }
                *(float2*)dst = v;
            }
        }
    }
}

// ---------------------------------------------------------------------------
// Flash attention (unchanged from R1): one CTA per (b, h, 64-row q tile).
// ---------------------------------------------------------------------------
__global__ __launch_bounds__(256) void attn_kernel(
    const float* __restrict__ bias,
    const float* __restrict__ Q,
    const float* __restrict__ K,
    const float* __restrict__ V,
    float* __restrict__ out)
{
    __shared__ float QsT[64][64];   // [hd][r]
    __shared__ float KsT[64][64];   // [hd][c], reused as Ps[c][r] after GEMM1
    __shared__ float Vs [64][64];   // [c][hd]

    const int tid = threadIdx.x;
    const int tx  = tid & 15;
    const int ty  = tid >> 4;
    const int q0  = blockIdx.x * 64;
    const int h   = blockIdx.y;
    const int b   = blockIdx.z;

    const float* Qp = Q + ((size_t)(b * Hz + h)) * Sz * HDz;
    const float* Kp = K + ((size_t)(b * Hz + h)) * Sz * HDz;
    const float* Vp = V + ((size_t)(b * Hz + h)) * Sz * HDz;
    const float* biasp = bias + (size_t)b * Sz * Sz;

    for (int v = tid; v < 64 * 16; v += 256) {
        int row = v >> 4;
        int c4  = (v & 15) << 2;
        float4 q4 = *(const float4*)(Qp + (size_t)(q0 + row) * HDz + c4);
        QsT[c4+0][row] = q4.x; QsT[c4+1][row] = q4.y;
        QsT[c4+2][row] = q4.z; QsT[c4+3][row] = q4.w;
    }

    float o[4][4];
    float mrow[4], lrow[4];
#pragma unroll
    for (int i = 0; i < 4; i++) {
        mrow[i] = -1e30f; lrow[i] = 0.f;
#pragma unroll
        for (int j = 0; j < 4; j++) o[i][j] = 0.f;
    }

    for (int k0 = 0; k0 < Sz; k0 += 64) {
        __syncthreads();
        for (int v = tid; v < 64 * 16; v += 256) {
            int row = v >> 4;
            int c4  = (v & 15) << 2;
            float4 k4 = *(const float4*)(Kp + (size_t)(k0 + row) * HDz + c4);
            KsT[c4+0][row] = k4.x; KsT[c4+1][row] = k4.y;
            KsT[c4+2][row] = k4.z; KsT[c4+3][row] = k4.w;
            *(float4*)(&Vs[row][c4]) = *(const float4*)(Vp + (size_t)(k0 + row) * HDz + c4);
        }
        __syncthreads();

        float s[4][4];
#pragma unroll
        for (int i = 0; i < 4; i++) {
            float4 b4 = *(const float4*)(biasp + (size_t)(q0 + ty*4 + i) * Sz + k0 + tx*4);
            s[i][0] = b4.x; s[i][1] = b4.y; s[i][2] = b4.z; s[i][3] = b4.w;
        }
#pragma unroll 8
        for (int kk = 0; kk < 64; kk++) {
            float4 a4 = *(float4*)(&QsT[kk][ty * 4]);
            float4 c4 = *(float4*)(&KsT[kk][tx * 4]);
            float a[4] = {a4.x, a4.y, a4.z, a4.w};
            float c[4] = {c4.x, c4.y, c4.z, c4.w};
#pragma unroll
            for (int i = 0; i < 4; i++)
#pragma unroll
                for (int j = 0; j < 4; j++)
                    s[i][j] = fmaf(a[i], c[j], s[i][j]);
        }
        __syncthreads();

        float* Ps = &KsT[0][0];
#pragma unroll
        for (int i = 0; i < 4; i++) {
            float mx = fmaxf(fmaxf(s[i][0], s[i][1]), fmaxf(s[i][2], s[i][3]));
#pragma unroll
            for (int off = 8; off >= 1; off >>= 1)
                mx = fmaxf(mx, __shfl_xor_sync(0xffffffffu, mx, off, 16));
            float mnew  = fmaxf(mrow[i], mx);
            float alpha = __expf(mrow[i] - mnew);
            mrow[i] = mnew;
            float ps = 0.f;
#pragma unroll
            for (int j = 0; j < 4; j++) {
                float p = __expf(s[i][j] - mnew);
                ps += p;
                Ps[(tx * 4 + j) * 64 + (ty * 4 + i)] = p;
            }
#pragma unroll
            for (int off = 8; off >= 1; off >>= 1)
                ps += __shfl_xor_sync(0xffffffffu, ps, off, 16);
            lrow[i] = lrow[i] * alpha + ps;
            o[i][0] *= alpha; o[i][1] *= alpha; o[i][2] *= alpha; o[i][3] *= alpha;
        }
        __syncthreads();

#pragma unroll 8
        for (int c = 0; c < 64; c++) {
            float4 p4 = *(float4*)(Ps + c * 64 + ty * 4);
            float4 v4 = *(float4*)(&Vs[c][tx * 4]);
            float pa[4] = {p4.x, p4.y, p4.z, p4.w};
            float vb[4] = {v4.x, v4.y, v4.z, v4.w};
#pragma unroll
            for (int i = 0; i < 4; i++)
#pragma unroll
                for (int j = 0; j < 4; j++)
                    o[i][j] = fmaf(pa[i], vb[j], o[i][j]);
        }
    }

#pragma unroll
    for (int i = 0; i < 4; i++) {
        float inv = 1.0f / lrow[i];
        int m = q0 + ty * 4 + i;
        float4 r;
        r.x = o[i][0] * inv; r.y = o[i][1] * inv;
        r.z = o[i][2] * inv; r.w = o[i][3] * inv;
        *(float4*)(out + ((size_t)b * Sz + m) * Dz + h * HDz + tx * 4) = r;
    }
}

// ---------------------------------------------------------------------------
// Launch
// ---------------------------------------------------------------------------
extern "C" void kernel_launch(void* const* d_in, const int* in_sizes, int n_in,
                              void* d_out, int out_size)
{
    const float* query = (const float*)d_in[0];
    const float* key_  = (const float*)d_in[1];
    const float* value = (const float*)d_in[2];
    const float* bias  = (const float*)d_in[3];
    const float* Wq    = (const float*)d_in[4];
    const float* Wk    = (const float*)d_in[5];
    const float* Wv    = (const float*)d_in[6];
    const float* Wo    = (const float*)d_in[7];

    float *qp, *kp, *vp, *ap;
    cudaGetSymbolAddress((void**)&qp, g_q);
    cudaGetSymbolAddress((void**)&kp, g_k);
    cudaGetSymbolAddress((void**)&vp, g_v);
    cudaGetSymbolAddress((void**)&ap, g_att);

    cudaFuncSetAttribute(gemm_tc, cudaFuncAttributeMaxDynamicSharedMemorySize, GEMM_DSMEM);

    dim3 gg(Dz / 128, Mz / 128);   // (8, 64)
    gemm_tc<<<gg, 256, GEMM_DSMEM>>>(query, Wq, qp, 0.125f, 1);   // HD^-0.5
    gemm_tc<<<gg, 256, GEMM_DSMEM>>>(key_,  Wk, kp, 1.0f, 1);
    gemm_tc<<<gg, 256, GEMM_DSMEM>>>(value, Wv, vp, 1.0f, 1);

    attn_kernel<<<dim3(Sz / 64, Hz, Bz), 256>>>(bias, qp, kp, vp, ap);

    gemm_tc<<<gg, 256, GEMM_DSMEM>>>(ap, Wo, (float*)d_out, 1.0f, 0);
}

// round 5
// speedup vs baseline: 2.9178x; 2.1631x over previous
#include <cuda_runtime.h>
#include <cuda_bf16.h>
#include <cstdint>

// Problem constants
#define Bz  4
#define Sz  2048
#define Dz  1024
#define Hz  16
#define HDz 64
#define Mz  (Bz*Sz)   // 8192

// Scratch (allocations forbidden -> __device__ globals).
__device__ float g_q[(size_t)Bz*Hz*Sz*HDz];
__device__ float g_k[(size_t)Bz*Hz*Sz*HDz];
__device__ float g_v[(size_t)Bz*Hz*Sz*HDz];
__device__ float g_att[(size_t)Bz*Sz*Dz];

// ===========================================================================
// Helpers
// ===========================================================================
__device__ __forceinline__ uint32_t smem_u32(const void* p) {
    uint32_t a;
    asm("{ .reg .u64 t; cvta.to.shared.u64 t, %1; cvt.u32.u64 %0, t; }"
        : "=r"(a) : "l"(p));
    return a;
}

// pack two floats into bf16x2: lo -> low 16 bits (memory-order element 0)
__device__ __forceinline__ uint32_t pack_bf16x2(float lo, float hi) {
    uint32_t r;
    asm("cvt.rn.bf16x2.f32 %0, %1, %2;" : "=r"(r) : "f"(hi), "f"(lo));
    return r;
}

__device__ __forceinline__ void ldmatrix_x4(uint32_t* r, uint32_t addr) {
    asm volatile("ldmatrix.sync.aligned.m8n8.x4.shared.b16 {%0,%1,%2,%3}, [%4];"
        : "=r"(r[0]), "=r"(r[1]), "=r"(r[2]), "=r"(r[3]) : "r"(addr));
}

__device__ __forceinline__ void ldmatrix_x4_t(uint32_t* r, uint32_t addr) {
    asm volatile("ldmatrix.sync.aligned.m8n8.x4.trans.shared.b16 {%0,%1,%2,%3}, [%4];"
        : "=r"(r[0]), "=r"(r[1]), "=r"(r[2]), "=r"(r[3]) : "r"(addr));
}

__device__ __forceinline__ void mma_bf16(float* d, const uint32_t* a, const uint32_t* b) {
    asm volatile(
        "mma.sync.aligned.m16n8k16.row.col.f32.bf16.bf16.f32 "
        "{%0,%1,%2,%3}, {%4,%5,%6,%7}, {%8,%9}, {%0,%1,%2,%3};"
        : "+f"(d[0]), "+f"(d[1]), "+f"(d[2]), "+f"(d[3])
        : "r"(a[0]), "r"(a[1]), "r"(a[2]), "r"(a[3]), "r"(b[0]), "r"(b[1]));
}

// convert 8 fp32 (two float4) -> one 16B hi chunk + one 16B lo chunk, store
__device__ __forceinline__ void split_sts(uint32_t hi_addr, uint32_t lo_addr,
                                          float4 a, float4 b) {
    uint32_t h0 = pack_bf16x2(a.x, a.y);
    uint32_t h1 = pack_bf16x2(a.z, a.w);
    uint32_t h2 = pack_bf16x2(b.x, b.y);
    uint32_t h3 = pack_bf16x2(b.z, b.w);
    uint32_t l0, l1, l2, l3;
    float ea, eb;
    ea = __uint_as_float(h0 << 16); eb = __uint_as_float(h0 & 0xffff0000u);
    l0 = pack_bf16x2(a.x - ea, a.y - eb);
    ea = __uint_as_float(h1 << 16); eb = __uint_as_float(h1 & 0xffff0000u);
    l1 = pack_bf16x2(a.z - ea, a.w - eb);
    ea = __uint_as_float(h2 << 16); eb = __uint_as_float(h2 & 0xffff0000u);
    l2 = pack_bf16x2(b.x - ea, b.y - eb);
    ea = __uint_as_float(h3 << 16); eb = __uint_as_float(h3 & 0xffff0000u);
    l3 = pack_bf16x2(b.z - ea, b.w - eb);
    asm volatile("st.shared.v4.b32 [%0], {%1,%2,%3,%4};"
        :: "r"(hi_addr), "r"(h0), "r"(h1), "r"(h2), "r"(h3) : "memory");
    asm volatile("st.shared.v4.b32 [%0], {%1,%2,%3,%4};"
        :: "r"(lo_addr), "r"(l0), "r"(l1), "r"(l2), "r"(l3) : "memory");
}

// ===========================================================================
// Split-bf16 tensor-core GEMM (validated R4): C = X @ W^T
// ===========================================================================
#define GEMM_DSMEM (2 * 32768 + 1024)

__global__ __launch_bounds__(256) void gemm_tc(
    const float* __restrict__ X, const float* __restrict__ W,
    float* __restrict__ out, float scale, int split_heads)
{
    extern __shared__ __align__(16) char dsm[];
    const uint32_t sbase = (smem_u32(dsm) + 1023) & ~1023u;

    const int tid    = threadIdx.x;
    const int wid    = tid >> 5;
    const int lane   = tid & 31;
    const int warp_m = wid & 3;
    const int warp_n = wid >> 2;
    const int m0 = blockIdx.y * 128;
    const int n0 = blockIdx.x * 128;

    const int lr0 = tid >> 2;
    const int lc  = tid & 3;

    float acc[2][8][4];
#pragma unroll
    for (int i = 0; i < 2; i++)
#pragma unroll
        for (int j = 0; j < 8; j++)
#pragma unroll
            for (int t = 0; t < 4; t++) acc[i][j][t] = 0.f;

    float4 xa[4], xb[4];
#pragma unroll
    for (int j = 0; j < 2; j++) {
        int r = lr0 + j * 64;
        const float* pa = X + (size_t)(m0 + r) * Dz + lc * 8;
        const float* pb = W + (size_t)(n0 + r) * Dz + lc * 8;
        xa[2*j]   = *(const float4*)(pa);
        xa[2*j+1] = *(const float4*)(pa + 4);
        xb[2*j]   = *(const float4*)(pb);
        xb[2*j+1] = *(const float4*)(pb + 4);
    }

    for (int kc = 0; kc < 32; kc++) {
        const uint32_t bb = sbase + (kc & 1) * 32768;

#pragma unroll
        for (int j = 0; j < 2; j++) {
            int r = lr0 + j * 64;
            uint32_t phys = (uint32_t)(r * 64 + ((lc ^ ((r >> 1) & 3)) << 4));
            split_sts(bb + phys,            bb + 8192u + phys,  xa[2*j], xa[2*j+1]);
            split_sts(bb + 16384u + phys,   bb + 24576u + phys, xb[2*j], xb[2*j+1]);
        }
        __syncthreads();

        if (kc < 31) {
            const int k0 = (kc + 1) * 32;
#pragma unroll
            for (int j = 0; j < 2; j++) {
                int r = lr0 + j * 64;
                const float* pa = X + (size_t)(m0 + r) * Dz + k0 + lc * 8;
                const float* pb = W + (size_t)(n0 + r) * Dz + k0 + lc * 8;
                xa[2*j]   = *(const float4*)(pa);
                xa[2*j+1] = *(const float4*)(pa + 4);
                xb[2*j]   = *(const float4*)(pb);
                xb[2*j+1] = *(const float4*)(pb + 4);
            }
        }

#pragma unroll
        for (int ks = 0; ks < 2; ks++) {
            uint32_t ahi[2][4], alo[2][4];
            const int cA = ks * 2 + (lane >> 4);
#pragma unroll
            for (int mt = 0; mt < 2; mt++) {
                int r = warp_m * 32 + mt * 16 + (lane & 15);
                uint32_t phys = (uint32_t)(r * 64 + ((cA ^ ((r >> 1) & 3)) << 4));
                ldmatrix_x4(ahi[mt], bb + phys);
                ldmatrix_x4(alo[mt], bb + 8192u + phys);
            }
            const int cB = ks * 2 + ((lane >> 3) & 1);
            const int rB = warp_n * 64 + (lane & 7) + ((lane & 16) >> 1);
#pragma unroll
            for (int np = 0; np < 4; np++) {
                uint32_t bh[4], bl[4];
                int r = rB + np * 16;
                uint32_t phys = (uint32_t)(r * 64 + ((cB ^ ((r >> 1) & 3)) << 4));
                ldmatrix_x4(bh, bb + 16384u + phys);
                ldmatrix_x4(bl, bb + 24576u + phys);
#pragma unroll
                for (int mt = 0; mt < 2; mt++) {
#pragma unroll
                    for (int half = 0; half < 2; half++) {
                        float* d = acc[mt][np * 2 + half];
                        mma_bf16(d, ahi[mt], bh + half * 2);
                        mma_bf16(d, ahi[mt], bl + half * 2);
                        mma_bf16(d, alo[mt], bh + half * 2);
                    }
                }
            }
        }
        __syncthreads();
    }

    const int r0 = lane >> 2;
    const int c0 = (lane & 3) * 2;
#pragma unroll
    for (int mt = 0; mt < 2; mt++) {
#pragma unroll
        for (int nt = 0; nt < 8; nt++) {
#pragma unroll
            for (int rr = 0; rr < 2; rr++) {
                int m = m0 + warp_m * 32 + mt * 16 + r0 + rr * 8;
                int n = n0 + warp_n * 64 + nt * 8 + c0;
                float2 v;
                v.x = acc[mt][nt][rr * 2 + 0] * scale;
                v.y = acc[mt][nt][rr * 2 + 1] * scale;
                float* dst;
                if (split_heads) {
                    int b = m >> 11, s = m & (Sz - 1);
                    int h = n >> 6, hd = n & 63;
                    dst = out + (((size_t)(b * Hz + h)) * Sz + s) * HDz + hd;
                } else {
                    dst = out + (size_t)m * Dz + n;
                }
                *(float2*)dst = v;
            }
        }
    }
}

// ===========================================================================
// Tensor-core flash attention.
// CTA: 128 q-rows of one (b,h). 8 warps, warp w owns q rows 16w..16w+15.
// Per 64-key iter: S = QK^T (split-bf16, 3 products) + bias, online softmax
// in registers, O += P V (split P and V, 3 products). P stays in registers
// (C-fragment == A-fragment layout). V read via ldmatrix.trans.
// SMEM: Qhi 16K | Qlo 16K | 2 x {Khi 8K, Klo 8K, Vhi 8K, Vlo 8K}.
// Rows are 128B (64 bf16); 16B chunk swizzle: phys = c ^ (row & 7).
// ===========================================================================
#define ATTN_DSMEM (32768 + 2 * 32768 + 128)

__global__ __launch_bounds__(256) void attn_tc(
    const float* __restrict__ bias,
    const float* __restrict__ Q,
    const float* __restrict__ K,
    const float* __restrict__ V,
    float* __restrict__ out)
{
    extern __shared__ __align__(16) char dsm[];
    const uint32_t sb  = (smem_u32(dsm) + 127) & ~127u;
    const uint32_t Qhi = sb, Qlo = sb + 16384u;

    const int tid  = threadIdx.x;
    const int wid  = tid >> 5;
    const int lane = tid & 31;
    const int q0 = blockIdx.x * 128;
    const int h  = blockIdx.y;
    const int b  = blockIdx.z;

    const size_t head_off = ((size_t)(b * Hz + h)) * Sz * HDz;
    const float* Qp = Q + head_off + (size_t)q0 * HDz;
    const float* Kp = K + head_off;
    const float* Vp = V + head_off;
    const float* bp = bias + (size_t)b * Sz * Sz + (size_t)q0 * Sz;

    // ---- load Q tile 128x64 -> hi/lo (once)
    {
        int row = tid >> 1, half = tid & 1;
        const float* src = Qp + (size_t)row * HDz + half * 32;
#pragma unroll
        for (int i = 0; i < 4; i++) {
            float4 x0 = *(const float4*)(src + i * 8);
            float4 x1 = *(const float4*)(src + i * 8 + 4);
            int c = half * 4 + i;
            uint32_t addr = (uint32_t)(row * 128 + ((c ^ (row & 7)) << 4));
            split_sts(Qhi + addr, Qlo + addr, x0, x1);
        }
    }

    // ---- prefetch K/V iter 0
    const int lrow = tid >> 2;      // key row 0..63
    const int lqd  = tid & 3;       // col quarter
    float4 pk[4], pv[4];
    {
        const float* ks = Kp + (size_t)lrow * HDz + lqd * 16;
        const float* vs = Vp + (size_t)lrow * HDz + lqd * 16;
#pragma unroll
        for (int j = 0; j < 4; j++) {
            pk[j] = *(const float4*)(ks + j * 4);
            pv[j] = *(const float4*)(vs + j * 4);
        }
    }
    __syncthreads();   // Q tile visible

    float o[8][4];
#pragma unroll
    for (int i = 0; i < 8; i++)
#pragma unroll
        for (int j = 0; j < 4; j++) o[i][j] = 0.f;
    float mr0 = -1e30f, mr1 = -1e30f, l0 = 0.f, l1 = 0.f;

    const int rA   = wid * 16 + (lane >> 2);        // row for frag slots 0,1
    const int cA0  = (lane & 3) * 2;

    for (int kc = 0; kc < 32; kc++) {
        const uint32_t bb  = sb + 32768u + (uint32_t)(kc & 1) * 32768u;
        const uint32_t Khi = bb, Klo = bb + 8192u, Vhi = bb + 16384u, Vlo = bb + 24576u;

        // ---- STS K/V (convert + split + swizzle)
#pragma unroll
        for (int j = 0; j < 2; j++) {
            int c = lqd * 2 + j;
            uint32_t addr = (uint32_t)(lrow * 128 + ((c ^ (lrow & 7)) << 4));
            split_sts(Khi + addr, Klo + addr, pk[2*j], pk[2*j+1]);
            split_sts(Vhi + addr, Vlo + addr, pv[2*j], pv[2*j+1]);
        }
        __syncthreads();

        // ---- prefetch next K/V tile
        if (kc < 31) {
            const float* ks = Kp + (size_t)((kc + 1) * 64 + lrow) * HDz + lqd * 16;
            const float* vs = Vp + (size_t)((kc + 1) * 64 + lrow) * HDz + lqd * 16;
#pragma unroll
            for (int j = 0; j < 4; j++) {
                pk[j] = *(const float4*)(ks + j * 4);
                pv[j] = *(const float4*)(vs + j * 4);
            }
        }

        // ---- bias prefetch (lands during QK mma chain)
        float2 br[2][8];
#pragma unroll
        for (int rr = 0; rr < 2; rr++)
#pragma unroll
            for (int nt = 0; nt < 8; nt++)
                br[rr][nt] = *(const float2*)(bp + (size_t)(rA + rr * 8) * Sz
                                               + kc * 64 + nt * 8 + cA0);

        // ---- S = Q K^T (split-bf16)
        float s[8][4];
#pragma unroll
        for (int i = 0; i < 8; i++)
#pragma unroll
            for (int j = 0; j < 4; j++) s[i][j] = 0.f;

#pragma unroll
        for (int ks = 0; ks < 4; ks++) {
            uint32_t ah[4], al[4];
            {
                int r = wid * 16 + (lane & 15);
                int c = ks * 2 + (lane >> 4);
                uint32_t ad = (uint32_t)(r * 128 + ((c ^ (r & 7)) << 4));
                ldmatrix_x4(ah, Qhi + ad);
                ldmatrix_x4(al, Qlo + ad);
            }
            const int cB = ks * 2 + ((lane >> 3) & 1);
            const int rB = (lane & 7) + ((lane & 16) >> 1);
#pragma unroll
            for (int np = 0; np < 4; np++) {
                uint32_t bh[4], bl[4];
                int r = rB + np * 16;
                uint32_t bd = (uint32_t)(r * 128 + ((cB ^ (r & 7)) << 4));
                ldmatrix_x4(bh, Khi + bd);
                ldmatrix_x4(bl, Klo + bd);
#pragma unroll
                for (int half = 0; half < 2; half++) {
                    float* d = s[np * 2 + half];
                    mma_bf16(d, ah, bh + half * 2);
                    mma_bf16(d, ah, bl + half * 2);
                    mma_bf16(d, al, bh + half * 2);
                }
            }
        }

        // ---- online softmax (rows rA, rA+8)
        float mx0 = -1e30f, mx1 = -1e30f;
#pragma unroll
        for (int nt = 0; nt < 8; nt++) {
            s[nt][0] += br[0][nt].x;  s[nt][1] += br[0][nt].y;
            s[nt][2] += br[1][nt].x;  s[nt][3] += br[1][nt].y;
            mx0 = fmaxf(mx0, fmaxf(s[nt][0], s[nt][1]));
            mx1 = fmaxf(mx1, fmaxf(s[nt][2], s[nt][3]));
        }
        mx0 = fmaxf(mx0, __shfl_xor_sync(0xffffffffu, mx0, 1));
        mx0 = fmaxf(mx0, __shfl_xor_sync(0xffffffffu, mx0, 2));
        mx1 = fmaxf(mx1, __shfl_xor_sync(0xffffffffu, mx1, 1));
        mx1 = fmaxf(mx1, __shfl_xor_sync(0xffffffffu, mx1, 2));

        float mn0 = fmaxf(mr0, mx0), mn1 = fmaxf(mr1, mx1);
        float a0 = __expf(mr0 - mn0), a1 = __expf(mr1 - mn1);
        mr0 = mn0; mr1 = mn1;

        float ps0 = 0.f, ps1 = 0.f;
#pragma unroll
        for (int nt = 0; nt < 8; nt++) {
            s[nt][0] = __expf(s[nt][0] - mn0);  ps0 += s[nt][0];
            s[nt][1] = __expf(s[nt][1] - mn0);  ps0 += s[nt][1];
            s[nt][2] = __expf(s[nt][2] - mn1);  ps1 += s[nt][2];
            s[nt][3] = __expf(s[nt][3] - mn1);  ps1 += s[nt][3];
        }
        ps0 += __shfl_xor_sync(0xffffffffu, ps0, 1);
        ps0 += __shfl_xor_sync(0xffffffffu, ps0, 2);
        ps1 += __shfl_xor_sync(0xffffffffu, ps1, 1);
        ps1 += __shfl_xor_sync(0xffffffffu, ps1, 2);
        l0 = l0 * a0 + ps0;
        l1 = l1 * a1 + ps1;
#pragma unroll
        for (int nt = 0; nt < 8; nt++) {
            o[nt][0] *= a0; o[nt][1] *= a0;
            o[nt][2] *= a1; o[nt][3] *= a1;
        }

        // ---- O += P V  (P from registers; V via ldmatrix.trans)
#pragma unroll
        for (int ks = 0; ks < 4; ks++) {
            uint32_t pah[4], pal[4];
#pragma unroll
            for (int j = 0; j < 4; j++) {
                float x0 = s[2 * ks + (j >> 1)][(j & 1) * 2 + 0];
                float x1 = s[2 * ks + (j >> 1)][(j & 1) * 2 + 1];
                uint32_t hh = pack_bf16x2(x0, x1);
                float e0 = __uint_as_float(hh << 16);
                float e1 = __uint_as_float(hh & 0xffff0000u);
                pah[j] = hh;
                pal[j] = pack_bf16x2(x0 - e0, x1 - e1);
            }
            const int rV = ks * 16 + (lane & 7) + (lane & 8);
#pragma unroll
            for (int np = 0; np < 4; np++) {
                int c = np * 2 + (lane >> 4);
                uint32_t vd = (uint32_t)(rV * 128 + ((c ^ (rV & 7)) << 4));
                uint32_t vh[4], vl[4];
                ldmatrix_x4_t(vh, Vhi + vd);
                ldmatrix_x4_t(vl, Vlo + vd);
                float* d0 = o[np * 2 + 0];
                float* d1 = o[np * 2 + 1];
                mma_bf16(d0, pah, vh);      mma_bf16(d0, pal, vh);
                mma_bf16(d0, pah, vl);
                mma_bf16(d1, pah, vh + 2);  mma_bf16(d1, pal, vh + 2);
                mma_bf16(d1, pah, vl + 2);
            }
        }
        __syncthreads();   // compute(buf) done before it is overwritten
    }

    // ---- normalize and store merged-head layout [B,S,D]
    float inv0 = 1.0f / l0, inv1 = 1.0f / l1;
#pragma unroll
    for (int rr = 0; rr < 2; rr++) {
        int m = q0 + rA + rr * 8;
        float inv = rr ? inv1 : inv0;
        float* dst = out + ((size_t)b * Sz + m) * Dz + h * HDz;
#pragma unroll
        for (int nt = 0; nt < 8; nt++) {
            float2 v;
            v.x = o[nt][rr * 2 + 0] * inv;
            v.y = o[nt][rr * 2 + 1] * inv;
            *(float2*)(dst + nt * 8 + cA0) = v;
        }
    }
}

// ---------------------------------------------------------------------------
// Launch
// ---------------------------------------------------------------------------
extern "C" void kernel_launch(void* const* d_in, const int* in_sizes, int n_in,
                              void* d_out, int out_size)
{
    const float* query = (const float*)d_in[0];
    const float* key_  = (const float*)d_in[1];
    const float* value = (const float*)d_in[2];
    const float* bias  = (const float*)d_in[3];
    const float* Wq    = (const float*)d_in[4];
    const float* Wk    = (const float*)d_in[5];
    const float* Wv    = (const float*)d_in[6];
    const float* Wo    = (const float*)d_in[7];

    float *qp, *kp, *vp, *ap;
    cudaGetSymbolAddress((void**)&qp, g_q);
    cudaGetSymbolAddress((void**)&kp, g_k);
    cudaGetSymbolAddress((void**)&vp, g_v);
    cudaGetSymbolAddress((void**)&ap, g_att);

    cudaFuncSetAttribute(gemm_tc, cudaFuncAttributeMaxDynamicSharedMemorySize, GEMM_DSMEM);
    cudaFuncSetAttribute(attn_tc, cudaFuncAttributeMaxDynamicSharedMemorySize, ATTN_DSMEM);

    dim3 gg(Dz / 128, Mz / 128);   // (8, 64)
    gemm_tc<<<gg, 256, GEMM_DSMEM>>>(query, Wq, qp, 0.125f, 1);   // HD^-0.5
    gemm_tc<<<gg, 256, GEMM_DSMEM>>>(key_,  Wk, kp, 1.0f, 1);
    gemm_tc<<<gg, 256, GEMM_DSMEM>>>(value, Wv, vp, 1.0f, 1);

    attn_tc<<<dim3(Sz / 128, Hz, Bz), 256, ATTN_DSMEM>>>(bias, qp, kp, vp, ap);

    gemm_tc<<<gg, 256, GEMM_DSMEM>>>(ap, Wo, (float*)d_out, 1.0f, 0);
}

// round 7
// speedup vs baseline: 3.4968x; 1.1985x over previous
#include <cuda_runtime.h>
#include <cuda_bf16.h>
#include <cstdint>

// Problem constants
#define Bz  4
#define Sz  2048
#define Dz  1024
#define Hz  16
#define HDz 64
#define Mz  (Bz*Sz)   // 8192

#define LOG2E 1.4426950408889634f

// Scratch (allocations forbidden -> __device__ globals).
__device__ __align__(128) __nv_bfloat16 g_qh[(size_t)Bz*Hz*Sz*HDz];
__device__ __align__(128) __nv_bfloat16 g_ql[(size_t)Bz*Hz*Sz*HDz];
__device__ __align__(128) __nv_bfloat16 g_kh[(size_t)Bz*Hz*Sz*HDz];
__device__ __align__(128) __nv_bfloat16 g_kl[(size_t)Bz*Hz*Sz*HDz];
__device__ __align__(128) __nv_bfloat16 g_vh[(size_t)Bz*Hz*Sz*HDz];
__device__ __align__(128) __nv_bfloat16 g_vl[(size_t)Bz*Hz*Sz*HDz];
__device__ __align__(128) float g_att[(size_t)Bz*Sz*Dz];

// ===========================================================================
// Helpers
// ===========================================================================
__device__ __forceinline__ uint32_t smem_u32(const void* p) {
    uint32_t a;
    asm("{ .reg .u64 t; cvta.to.shared.u64 t, %1; cvt.u32.u64 %0, t; }"
        : "=r"(a) : "l"(p));
    return a;
}

// pack two floats into bf16x2: first arg -> low 16 bits (memory element 0)
__device__ __forceinline__ uint32_t pack_bf16x2(float lo, float hi) {
    uint32_t r;
    asm("cvt.rn.bf16x2.f32 %0, %1, %2;" : "=r"(r) : "f"(hi), "f"(lo));
    return r;
}

__device__ __forceinline__ float ex2f(float x) {
    float y;
    asm("ex2.approx.ftz.f32 %0, %1;" : "=f"(y) : "f"(x));
    return y;
}

__device__ __forceinline__ void ldmatrix_x4(uint32_t* r, uint32_t addr) {
    asm volatile("ldmatrix.sync.aligned.m8n8.x4.shared.b16 {%0,%1,%2,%3}, [%4];"
        : "=r"(r[0]), "=r"(r[1]), "=r"(r[2]), "=r"(r[3]) : "r"(addr));
}

__device__ __forceinline__ void ldmatrix_x4_t(uint32_t* r, uint32_t addr) {
    asm volatile("ldmatrix.sync.aligned.m8n8.x4.trans.shared.b16 {%0,%1,%2,%3}, [%4];"
        : "=r"(r[0]), "=r"(r[1]), "=r"(r[2]), "=r"(r[3]) : "r"(addr));
}

__device__ __forceinline__ void mma_bf16(float* d, const uint32_t* a, const uint32_t* b) {
    asm volatile(
        "mma.sync.aligned.m16n8k16.row.col.f32.bf16.bf16.f32 "
        "{%0,%1,%2,%3}, {%4,%5,%6,%7}, {%8,%9}, {%0,%1,%2,%3};"
        : "+f"(d[0]), "+f"(d[1]), "+f"(d[2]), "+f"(d[3])
        : "r"(a[0]), "r"(a[1]), "r"(a[2]), "r"(a[3]), "r"(b[0]), "r"(b[1]));
}

// convert 8 fp32 -> 16B hi chunk + 16B lo chunk in SMEM (GEMM loader)
__device__ __forceinline__ void split_sts(uint32_t hi_addr, uint32_t lo_addr,
                                          float4 a, float4 b) {
    uint32_t h0 = pack_bf16x2(a.x, a.y);
    uint32_t h1 = pack_bf16x2(a.z, a.w);
    uint32_t h2 = pack_bf16x2(b.x, b.y);
    uint32_t h3 = pack_bf16x2(b.z, b.w);
    uint32_t l0, l1, l2, l3;
    float ea, eb;
    ea = __uint_as_float(h0 << 16); eb = __uint_as_float(h0 & 0xffff0000u);
    l0 = pack_bf16x2(a.x - ea, a.y - eb);
    ea = __uint_as_float(h1 << 16); eb = __uint_as_float(h1 & 0xffff0000u);
    l1 = pack_bf16x2(a.z - ea, a.w - eb);
    ea = __uint_as_float(h2 << 16); eb = __uint_as_float(h2 & 0xffff0000u);
    l2 = pack_bf16x2(b.x - ea, b.y - eb);
    ea = __uint_as_float(h3 << 16); eb = __uint_as_float(h3 & 0xffff0000u);
    l3 = pack_bf16x2(b.z - ea, b.w - eb);
    asm volatile("st.shared.v4.b32 [%0], {%1,%2,%3,%4};"
        :: "r"(hi_addr), "r"(h0), "r"(h1), "r"(h2), "r"(h3) : "memory");
    asm volatile("st.shared.v4.b32 [%0], {%1,%2,%3,%4};"
        :: "r"(lo_addr), "r"(l0), "r"(l1), "r"(l2), "r"(l3) : "memory");
}

#define CP_A16(dst, src) \
    asm volatile("cp.async.cg.shared.global [%0], [%1], 16;" \
                 :: "r"(dst), "l"(src) : "memory")
#define CP_COMMIT() asm volatile("cp.async.commit_group;" ::: "memory")
#define CP_WAIT(n)  asm volatile("cp.async.wait_group %0;" :: "n"(n) : "memory")

// ===========================================================================
// Split-bf16 tensor-core GEMM (validated R4): C = X @ W^T
// mode 0: fp32 out [M,N].  mode 1: split-heads bf16 hi/lo out [B,H,S,HD].
// ===========================================================================
#define GEMM_DSMEM (2 * 32768 + 1024)

__global__ __launch_bounds__(256) void gemm_tc(
    const float* __restrict__ X, const float* __restrict__ W,
    float* __restrict__ outF,
    __nv_bfloat16* __restrict__ outH, __nv_bfloat16* __restrict__ outL,
    float scale, int mode)
{
    extern __shared__ __align__(16) char dsm[];
    const uint32_t sbase = (smem_u32(dsm) + 1023) & ~1023u;

    const int tid    = threadIdx.x;
    const int wid    = tid >> 5;
    const int lane   = tid & 31;
    const int warp_m = wid & 3;
    const int warp_n = wid >> 2;
    const int m0 = blockIdx.y * 128;
    const int n0 = blockIdx.x * 128;

    const int lr0 = tid >> 2;
    const int lc  = tid & 3;

    float acc[2][8][4];
#pragma unroll
    for (int i = 0; i < 2; i++)
#pragma unroll
        for (int j = 0; j < 8; j++)
#pragma unroll
            for (int t = 0; t < 4; t++) acc[i][j][t] = 0.f;

    float4 xa[4], xb[4];
#pragma unroll
    for (int j = 0; j < 2; j++) {
        int r = lr0 + j * 64;
        const float* pa = X + (size_t)(m0 + r) * Dz + lc * 8;
        const float* pb = W + (size_t)(n0 + r) * Dz + lc * 8;
        xa[2*j]   = *(const float4*)(pa);
        xa[2*j+1] = *(const float4*)(pa + 4);
        xb[2*j]   = *(const float4*)(pb);
        xb[2*j+1] = *(const float4*)(pb + 4);
    }

    for (int kc = 0; kc < 32; kc++) {
        const uint32_t bb = sbase + (kc & 1) * 32768;

#pragma unroll
        for (int j = 0; j < 2; j++) {
            int r = lr0 + j * 64;
            uint32_t phys = (uint32_t)(r * 64 + ((lc ^ ((r >> 1) & 3)) << 4));
            split_sts(bb + phys,            bb + 8192u + phys,  xa[2*j], xa[2*j+1]);
            split_sts(bb + 16384u + phys,   bb + 24576u + phys, xb[2*j], xb[2*j+1]);
        }
        __syncthreads();

        if (kc < 31) {
            const int k0 = (kc + 1) * 32;
#pragma unroll
            for (int j = 0; j < 2; j++) {
                int r = lr0 + j * 64;
                const float* pa = X + (size_t)(m0 + r) * Dz + k0 + lc * 8;
                const float* pb = W + (size_t)(n0 + r) * Dz + k0 + lc * 8;
                xa[2*j]   = *(const float4*)(pa);
                xa[2*j+1] = *(const float4*)(pa + 4);
                xb[2*j]   = *(const float4*)(pb);
                xb[2*j+1] = *(const float4*)(pb + 4);
            }
        }

#pragma unroll
        for (int ks = 0; ks < 2; ks++) {
            uint32_t ahi[2][4], alo[2][4];
            const int cA = ks * 2 + (lane >> 4);
#pragma unroll
            for (int mt = 0; mt < 2; mt++) {
                int r = warp_m * 32 + mt * 16 + (lane & 15);
                uint32_t phys = (uint32_t)(r * 64 + ((cA ^ ((r >> 1) & 3)) << 4));
                ldmatrix_x4(ahi[mt], bb + phys);
                ldmatrix_x4(alo[mt], bb + 8192u + phys);
            }
            const int cB = ks * 2 + ((lane >> 3) & 1);
            const int rB = warp_n * 64 + (lane & 7) + ((lane & 16) >> 1);
#pragma unroll
            for (int np = 0; np < 4; np++) {
                uint32_t bh[4], bl[4];
                int r = rB + np * 16;
                uint32_t phys = (uint32_t)(r * 64 + ((cB ^ ((r >> 1) & 3)) << 4));
                ldmatrix_x4(bh, bb + 16384u + phys);
                ldmatrix_x4(bl, bb + 24576u + phys);
#pragma unroll
                for (int mt = 0; mt < 2; mt++) {
#pragma unroll
                    for (int half = 0; half < 2; half++) {
                        float* d = acc[mt][np * 2 + half];
                        mma_bf16(d, ahi[mt], bh + half * 2);
                        mma_bf16(d, ahi[mt], bl + half * 2);
                        mma_bf16(d, alo[mt], bh + half * 2);
                    }
                }
            }
        }
        __syncthreads();
    }

    const int r0 = lane >> 2;
    const int c0 = (lane & 3) * 2;
#pragma unroll
    for (int mt = 0; mt < 2; mt++) {
#pragma unroll
        for (int nt = 0; nt < 8; nt++) {
#pragma unroll
            for (int rr = 0; rr < 2; rr++) {
                int m = m0 + warp_m * 32 + mt * 16 + r0 + rr * 8;
                int n = n0 + warp_n * 64 + nt * 8 + c0;
                float v0 = acc[mt][nt][rr * 2 + 0] * scale;
                float v1 = acc[mt][nt][rr * 2 + 1] * scale;
                if (mode) {
                    int b = m >> 11, s = m & (Sz - 1);
                    int h = n >> 6, hd = n & 63;
                    size_t idx = (((size_t)(b * Hz + h)) * Sz + s) * HDz + hd;
                    uint32_t hw = pack_bf16x2(v0, v1);
                    float e0 = __uint_as_float(hw << 16);
                    float e1 = __uint_as_float(hw & 0xffff0000u);
                    uint32_t lw = pack_bf16x2(v0 - e0, v1 - e1);
                    *(uint32_t*)(outH + idx) = hw;
                    *(uint32_t*)(outL + idx) = lw;
                } else {
                    float2 v; v.x = v0; v.y = v1;
                    *(float2*)(outF + (size_t)m * Dz + n) = v;
                }
            }
        }
    }
}

// ===========================================================================
// Tensor-core flash attention v2.
// Inputs pre-split bf16 hi/lo. All tile loads via cp.async into swizzled
// SMEM (no conversion, no fp32 prefetch regs). Softmax in exp2 domain
// (Q pre-scaled by 0.125*log2e; bias folded via FMA with log2e).
// CTA: 128 q-rows, 8 warps, warp owns 16 rows. 2 CTAs/SM target.
// SMEM: Qhi 16K | Qlo 16K | 2 x {Khi 8K, Klo 8K, Vhi 8K, Vlo 8K} = 96K.
// Row = 128B (64 bf16), 16B chunk swizzle: phys_c = c ^ (row & 7).
// ===========================================================================
#define ATTN_DSMEM (32768 + 2 * 32768 + 128)

__global__ __launch_bounds__(256, 2) void attn_tc(
    const float* __restrict__ bias,
    const __nv_bfloat16* __restrict__ Qh, const __nv_bfloat16* __restrict__ Ql,
    const __nv_bfloat16* __restrict__ Kh, const __nv_bfloat16* __restrict__ Kl,
    const __nv_bfloat16* __restrict__ Vh, const __nv_bfloat16* __restrict__ Vl,
    float* __restrict__ out)
{
    extern __shared__ __align__(16) char dsm[];
    const uint32_t sb  = (smem_u32(dsm) + 127) & ~127u;
    const uint32_t Qhi = sb, Qlo = sb + 16384u;

    const int tid  = threadIdx.x;
    const int wid  = tid >> 5;
    const int lane = tid & 31;
    const int q0 = blockIdx.x * 128;
    const int h  = blockIdx.y;
    const int b  = blockIdx.z;

    const size_t head_off = ((size_t)(b * Hz + h)) * Sz * HDz;
    const __nv_bfloat16* Qhp = Qh + head_off + (size_t)q0 * HDz;
    const __nv_bfloat16* Qlp = Ql + head_off + (size_t)q0 * HDz;
    const float* bp = bias + (size_t)b * Sz * Sz + (size_t)q0 * Sz;

    const int lrow = tid >> 2;      // key row 0..63
    const int lqd  = tid & 3;       // chunk-pair selector

    // ---- group 0: Q tile + K/V tile 0
    {
        int row = tid >> 1, half = tid & 1;
#pragma unroll
        for (int i = 0; i < 4; i++) {
            int c = half * 4 + i;
            uint32_t ad = (uint32_t)(row * 128 + ((c ^ (row & 7)) << 4));
            CP_A16(Qhi + ad, Qhp + (size_t)row * HDz + c * 8);
            CP_A16(Qlo + ad, Qlp + (size_t)row * HDz + c * 8);
        }
    }
    const uint32_t buf0 = sb + 32768u;
#pragma unroll
    for (int j = 0; j < 2; j++) {
        int c = lqd * 2 + j;
        uint32_t ad = (uint32_t)(lrow * 128 + ((c ^ (lrow & 7)) << 4));
        size_t src = head_off + (size_t)lrow * HDz + c * 8;
        CP_A16(buf0 + ad,           Kh + src);
        CP_A16(buf0 + 8192u + ad,   Kl + src);
        CP_A16(buf0 + 16384u + ad,  Vh + src);
        CP_A16(buf0 + 24576u + ad,  Vl + src);
    }
    CP_COMMIT();
    // ---- group 1: K/V tile 1
    {
        const uint32_t buf1 = sb + 65536u;
#pragma unroll
        for (int j = 0; j < 2; j++) {
            int c = lqd * 2 + j;
            uint32_t ad = (uint32_t)(lrow * 128 + ((c ^ (lrow & 7)) << 4));
            size_t src = head_off + (size_t)(64 + lrow) * HDz + c * 8;
            CP_A16(buf1 + ad,           Kh + src);
            CP_A16(buf1 + 8192u + ad,   Kl + src);
            CP_A16(buf1 + 16384u + ad,  Vh + src);
            CP_A16(buf1 + 24576u + ad,  Vl + src);
        }
        CP_COMMIT();
    }

    float o[8][4];
#pragma unroll
    for (int i = 0; i < 8; i++)
#pragma unroll
        for (int j = 0; j < 4; j++) o[i][j] = 0.f;
    float mr0 = -1e30f, mr1 = -1e30f, l0 = 0.f, l1 = 0.f;

    const int rA  = wid * 16 + (lane >> 2);
    const int cA0 = (lane & 3) * 2;

    for (int kc = 0; kc < 32; kc++) {
        const uint32_t bb  = sb + 32768u + (uint32_t)(kc & 1) * 32768u;
        const uint32_t Khi = bb, Klo = bb + 8192u, Vhi = bb + 16384u, Vlo = bb + 24576u;

        if (kc < 31) CP_WAIT(1); else CP_WAIT(0);
        __syncthreads();

        // ---- bias prefetch (lands during QK mma chain)
        float2 br[2][8];
#pragma unroll
        for (int rr = 0; rr < 2; rr++)
#pragma unroll
            for (int nt = 0; nt < 8; nt++)
                br[rr][nt] = *(const float2*)(bp + (size_t)(rA + rr * 8) * Sz
                                               + kc * 64 + nt * 8 + cA0);

        // ---- S = Q K^T (split-bf16, exp2-scaled domain)
        float s[8][4];
#pragma unroll
        for (int i = 0; i < 8; i++)
#pragma unroll
            for (int j = 0; j < 4; j++) s[i][j] = 0.f;

#pragma unroll
        for (int ks = 0; ks < 4; ks++) {
            uint32_t ah[4], al[4];
            {
                int r = wid * 16 + (lane & 15);
                int c = ks * 2 + (lane >> 4);
                uint32_t ad = (uint32_t)(r * 128 + ((c ^ (r & 7)) << 4));
                ldmatrix_x4(ah, Qhi + ad);
                ldmatrix_x4(al, Qlo + ad);
            }
            const int cB = ks * 2 + ((lane >> 3) & 1);
            const int rB = (lane & 7) + ((lane & 16) >> 1);
#pragma unroll
            for (int np = 0; np < 4; np++) {
                uint32_t bh[4], bl[4];
                int r = rB + np * 16;
                uint32_t bd = (uint32_t)(r * 128 + ((cB ^ (r & 7)) << 4));
                ldmatrix_x4(bh, Khi + bd);
                ldmatrix_x4(bl, Klo + bd);
#pragma unroll
                for (int half = 0; half < 2; half++) {
                    float* d = s[np * 2 + half];
                    mma_bf16(d, ah, bh + half * 2);
                    mma_bf16(d, ah, bl + half * 2);
                    mma_bf16(d, al, bh + half * 2);
                }
            }
        }

        // ---- online softmax (base-2 domain), rows rA, rA+8
        float mx0 = -1e30f, mx1 = -1e30f;
#pragma unroll
        for (int nt = 0; nt < 8; nt++) {
            s[nt][0] = fmaf(br[0][nt].x, LOG2E, s[nt][0]);
            s[nt][1] = fmaf(br[0][nt].y, LOG2E, s[nt][1]);
            s[nt][2] = fmaf(br[1][nt].x, LOG2E, s[nt][2]);
            s[nt][3] = fmaf(br[1][nt].y, LOG2E, s[nt][3]);
            mx0 = fmaxf(mx0, fmaxf(s[nt][0], s[nt][1]));
            mx1 = fmaxf(mx1, fmaxf(s[nt][2], s[nt][3]));
        }
        mx0 = fmaxf(mx0, __shfl_xor_sync(0xffffffffu, mx0, 1));
        mx0 = fmaxf(mx0, __shfl_xor_sync(0xffffffffu, mx0, 2));
        mx1 = fmaxf(mx1, __shfl_xor_sync(0xffffffffu, mx1, 1));
        mx1 = fmaxf(mx1, __shfl_xor_sync(0xffffffffu, mx1, 2));

        float mn0 = fmaxf(mr0, mx0), mn1 = fmaxf(mr1, mx1);
        float a0 = ex2f(mr0 - mn0), a1 = ex2f(mr1 - mn1);
        mr0 = mn0; mr1 = mn1;

        float ps0 = 0.f, ps1 = 0.f;
#pragma unroll
        for (int nt = 0; nt < 8; nt++) {
            s[nt][0] = ex2f(s[nt][0] - mn0);  ps0 += s[nt][0];
            s[nt][1] = ex2f(s[nt][1] - mn0);  ps0 += s[nt][1];
            s[nt][2] = ex2f(s[nt][2] - mn1);  ps1 += s[nt][2];
            s[nt][3] = ex2f(s[nt][3] - mn1);  ps1 += s[nt][3];
        }
        ps0 += __shfl_xor_sync(0xffffffffu, ps0, 1);
        ps0 += __shfl_xor_sync(0xffffffffu, ps0, 2);
        ps1 += __shfl_xor_sync(0xffffffffu, ps1, 1);
        ps1 += __shfl_xor_sync(0xffffffffu, ps1, 2);
        l0 = l0 * a0 + ps0;
        l1 = l1 * a1 + ps1;
#pragma unroll
        for (int nt = 0; nt < 8; nt++) {
            o[nt][0] *= a0; o[nt][1] *= a0;
            o[nt][2] *= a1; o[nt][3] *= a1;
        }

        // ---- O += P V  (P packed from registers; V via ldmatrix.trans)
#pragma unroll
        for (int ks = 0; ks < 4; ks++) {
            uint32_t pah[4], pal[4];
#pragma unroll
            for (int j = 0; j < 4; j++) {
                float x0 = s[2 * ks + (j >> 1)][(j & 1) * 2 + 0];
                float x1 = s[2 * ks + (j >> 1)][(j & 1) * 2 + 1];
                uint32_t hh = pack_bf16x2(x0, x1);
                float e0 = __uint_as_float(hh << 16);
                float e1 = __uint_as_float(hh & 0xffff0000u);
                pah[j] = hh;
                pal[j] = pack_bf16x2(x0 - e0, x1 - e1);
            }
            const int rV = ks * 16 + (lane & 7) + (lane & 8);
#pragma unroll
            for (int np = 0; np < 4; np++) {
                int c = np * 2 + (lane >> 4);
                uint32_t vd = (uint32_t)(rV * 128 + ((c ^ (rV & 7)) << 4));
                uint32_t vh[4], vl[4];
                ldmatrix_x4_t(vh, Vhi + vd);
                ldmatrix_x4_t(vl, Vlo + vd);
                float* d0 = o[np * 2 + 0];
                float* d1 = o[np * 2 + 1];
                mma_bf16(d0, pah, vh);      mma_bf16(d0, pal, vh);
                mma_bf16(d0, pah, vl);
                mma_bf16(d1, pah, vh + 2);  mma_bf16(d1, pal, vh + 2);
                mma_bf16(d1, pah, vl + 2);
            }
        }
        __syncthreads();   // all warps done with buf (kc&1) before refill

        // ---- refill this buffer with tile kc+2
        if (kc + 2 < 32) {
#pragma unroll
            for (int j = 0; j < 2; j++) {
                int c = lqd * 2 + j;
                uint32_t ad = (uint32_t)(lrow * 128 + ((c ^ (lrow & 7)) << 4));
                size_t src = head_off + (size_t)((kc + 2) * 64 + lrow) * HDz + c * 8;
                CP_A16(Khi + ad, Kh + src);
                CP_A16(Klo + ad, Kl + src);
                CP_A16(Vhi + ad, Vh + src);
                CP_A16(Vlo + ad, Vl + src);
            }
            CP_COMMIT();
        }
    }

    // ---- normalize and store merged-head layout [B,S,D]
    float inv0 = 1.0f / l0, inv1 = 1.0f / l1;
#pragma unroll
    for (int rr = 0; rr < 2; rr++) {
        int m = q0 + rA + rr * 8;
        float inv = rr ? inv1 : inv0;
        float* dst = out + ((size_t)b * Sz + m) * Dz + h * HDz;
#pragma unroll
        for (int nt = 0; nt < 8; nt++) {
            float2 v;
            v.x = o[nt][rr * 2 + 0] * inv;
            v.y = o[nt][rr * 2 + 1] * inv;
            *(float2*)(dst + nt * 8 + cA0) = v;
        }
    }
}

// ---------------------------------------------------------------------------
// Launch
// ---------------------------------------------------------------------------
extern "C" void kernel_launch(void* const* d_in, const int* in_sizes, int n_in,
                              void* d_out, int out_size)
{
    const float* query = (const float*)d_in[0];
    const float* key_  = (const float*)d_in[1];
    const float* value = (const float*)d_in[2];
    const float* bias  = (const float*)d_in[3];
    const float* Wq    = (const float*)d_in[4];
    const float* Wk    = (const float*)d_in[5];
    const float* Wv    = (const float*)d_in[6];
    const float* Wo    = (const float*)d_in[7];

    __nv_bfloat16 *qh, *ql, *kh, *kl, *vh, *vl;
    float *ap;
    cudaGetSymbolAddress((void**)&qh, g_qh);
    cudaGetSymbolAddress((void**)&ql, g_ql);
    cudaGetSymbolAddress((void**)&kh, g_kh);
    cudaGetSymbolAddress((void**)&kl, g_kl);
    cudaGetSymbolAddress((void**)&vh, g_vh);
    cudaGetSymbolAddress((void**)&vl, g_vl);
    cudaGetSymbolAddress((void**)&ap, g_att);

    cudaFuncSetAttribute(gemm_tc, cudaFuncAttributeMaxDynamicSharedMemorySize, GEMM_DSMEM);
    cudaFuncSetAttribute(attn_tc, cudaFuncAttributeMaxDynamicSharedMemorySize, ATTN_DSMEM);

    dim3 gg(Dz / 128, Mz / 128);   // (8, 64)
    gemm_tc<<<gg, 256, GEMM_DSMEM>>>(query, Wq, nullptr, qh, ql, 0.125f * LOG2E, 1);
    gemm_tc<<<gg, 256, GEMM_DSMEM>>>(key_,  Wk, nullptr, kh, kl, 1.0f, 1);
    gemm_tc<<<gg, 256, GEMM_DSMEM>>>(value, Wv, nullptr, vh, vl, 1.0f, 1);

    attn_tc<<<dim3(Sz / 128, Hz, Bz), 256, ATTN_DSMEM>>>(bias, qh, ql, kh, kl, vh, vl, ap);

    gemm_tc<<<gg, 256, GEMM_DSMEM>>>(ap, Wo, (float*)d_out, nullptr, nullptr, 1.0f, 0);
}